// round 2
// baseline (speedup 1.0000x reference)
#include <cuda_runtime.h>

// Micromagnetic LLG RK4 solver — persistent kernel, NEIGHBOR-ONLY sync.
// One CTA per grid row (256 CTAs x 256 threads, one thread per cell).
// The 5-point stencil means CTA r only reads rows r-1 / r+1, so instead of a
// full grid barrier per RK4 stage we use per-CTA release/acquire stage
// counters: publish own stage, wait for the two neighbor rows only. The grid
// runs as a skew-tolerant wavefront. Stage data is AoS float4 (vector LDG/STG)
// in L2-resident __device__ buffers; horizontal neighbors come from a
// double-buffered shared-memory row.

#define NXg 256
#define NYg 256
#define PLANE (NXg * NYg)
#define TSTEPS 256
#define NSIG 2
#define NSRC 3
#define NPROBE 5
#define RELAXN 100
#define NBLK 256
#define NTHR 256

__device__ float4 g_m4 [PLANE];
__device__ float4 g_ta4[PLANE];
__device__ float4 g_tb4[PLANE];
__device__ unsigned g_stage[NBLK];   // zero-initialized; grows monotonically

__device__ __forceinline__ unsigned ld_acq(const unsigned* p) {
    unsigned v;
    asm volatile("ld.acquire.gpu.u32 %0, [%1];" : "=r"(v) : "l"(p) : "memory");
    return v;
}
__device__ __forceinline__ void st_rel(unsigned* p, unsigned v) {
    asm volatile("st.release.gpu.u32 [%0], %1;" :: "l"(p), "r"(v) : "memory");
}

struct Ctx {
    int idx, iN, iS;
    bool hasN, hasS;
    float bx, by, bz;
    float CEx, CD, hh;
};

// Publish own stage (release) and wait for both neighbor rows (acquire).
// scur is a uniform per-thread register tracking the published level.
__device__ __forceinline__ void publish_wait(int r, unsigned& scur,
                                             bool hasN, bool hasS) {
    __threadfence();          // make this thread's data stores gpu-visible
    __syncthreads();          // all CTA stores ordered before the publish
    scur++;
    if (threadIdx.x == 0) {
        st_rel(&g_stage[r], scur);
        if (hasN) while ((int)(ld_acq(&g_stage[r - 1]) - scur) < 0) { }
    }
    if (threadIdx.x == 32) {
        if (hasS) while ((int)(ld_acq(&g_stage[r + 1]) - scur) < 0) { }
    }
    __syncthreads();
}

// Store stage value to the global ping-pong buffer + the smem row slot.
__device__ __forceinline__ void stage_store(float4* __restrict__ buf,
                                            const Ctx& c, float4 u,
                                            float4* __restrict__ s_row) {
    __stcg(buf + c.idx, u);
    s_row[threadIdx.x + 1] = u;
    if (threadIdx.x == 0)        s_row[0]        = u;   // edge clamp (W)
    if (threadIdx.x == NTHR - 1) s_row[NTHR + 1] = u;   // edge clamp (E)
}

// LLG torque at own cell; vertical neighbors from global AoS buffer (L2),
// horizontal neighbors from the smem row, clamped edges use own value.
__device__ __forceinline__ float4 stage_torque(const float4* __restrict__ vbuf,
                                               const float4* __restrict__ s_row,
                                               const Ctx& c, float4 u,
                                               float bzAdd, float alpha, float inv)
{
    float4 nN = c.hasN ? __ldcg(vbuf + c.iN) : u;
    float4 nS = c.hasS ? __ldcg(vbuf + c.iS) : u;
    float4 nW = s_row[threadIdx.x];
    float4 nE = s_row[threadIdx.x + 2];

    float lx = nN.x + nS.x + nW.x + nE.x - 4.0f * u.x;
    float ly = nN.y + nS.y + nW.y + nE.y - 4.0f * u.y;
    float lz = nN.z + nS.z + nW.z + nE.z - 4.0f * u.z;

    float Bx = c.bx + c.CEx * lx;
    float By = c.by + c.CEx * ly;
    float Bz = c.bz + bzAdd + c.CEx * lz - c.CD * u.z;

    // c1 = u x B
    float c1x = u.y * Bz - u.z * By;
    float c1y = u.z * Bx - u.x * Bz;
    float c1z = u.x * By - u.y * Bx;
    // c2 = u x c1
    float c2x = u.y * c1z - u.z * c1y;
    float c2y = u.z * c1x - u.x * c1z;
    float c2z = u.x * c1y - u.y * c1x;
    // sot = C_SOT * (u x (u x p)), p=(0,1,0) -> (ux*uy, -(uz^2+ux^2), uy*uz)
    const float CS = 1.0e-4f;
    float4 t;
    t.x = -inv * (c1x + alpha * c2x) + CS * (u.x * u.y);
    t.y = -inv * (c1y + alpha * c2y) + CS * (-(u.z * u.z + u.x * u.x));
    t.z = -inv * (c1z + alpha * c2z) + CS * (u.y * u.z);
    t.w = 0.0f;
    return t;
}

// One RK4 step = 4 stages, each: torque -> store -> publish_wait.
// Invariant on entry/exit: level scur data published; smem slot = scur & 1.
__device__ __forceinline__ void rk4step(float4& m, const Ctx& c,
                                        float4 (*s_u)[NTHR + 2],
                                        float bzAdd, float alpha, float inv,
                                        int r, unsigned& scur)
{
    const float h2 = 0.5f * c.hh;
    float4 u = m;
    // stage 1 : input g_m4 (level scur)
    float4 k = stage_torque(g_m4, s_u[scur & 1], c, u, bzAdd, alpha, inv);
    float ax = k.x, ay = k.y, az = k.z;
    u.x = m.x + h2 * k.x; u.y = m.y + h2 * k.y; u.z = m.z + h2 * k.z;
    stage_store(g_ta4, c, u, s_u[(scur + 1) & 1]);
    publish_wait(r, scur, c.hasN, c.hasS);
    // stage 2 : input g_ta4
    k = stage_torque(g_ta4, s_u[scur & 1], c, u, bzAdd, alpha, inv);
    ax += 2.0f * k.x; ay += 2.0f * k.y; az += 2.0f * k.z;
    u.x = m.x + h2 * k.x; u.y = m.y + h2 * k.y; u.z = m.z + h2 * k.z;
    stage_store(g_tb4, c, u, s_u[(scur + 1) & 1]);
    publish_wait(r, scur, c.hasN, c.hasS);
    // stage 3 : input g_tb4
    k = stage_torque(g_tb4, s_u[scur & 1], c, u, bzAdd, alpha, inv);
    ax += 2.0f * k.x; ay += 2.0f * k.y; az += 2.0f * k.z;
    u.x = m.x + c.hh * k.x; u.y = m.y + c.hh * k.y; u.z = m.z + c.hh * k.z;
    stage_store(g_ta4, c, u, s_u[(scur + 1) & 1]);
    publish_wait(r, scur, c.hasN, c.hasS);
    // stage 4 : input g_ta4
    k = stage_torque(g_ta4, s_u[scur & 1], c, u, bzAdd, alpha, inv);
    const float h6 = c.hh * (1.0f / 6.0f);
    m.x += h6 * (ax + k.x);
    m.y += h6 * (ay + k.y);
    m.z += h6 * (az + k.z);
    stage_store(g_m4, c, m, s_u[(scur + 1) & 1]);
    publish_wait(r, scur, c.hasN, c.hasS);
}

__global__ void __launch_bounds__(NTHR, 2)
mm_kernel(const float* __restrict__ sig, const float* __restrict__ Bext,
          const float* __restrict__ MsatP, const int* __restrict__ srcP,
          const int* __restrict__ probeP, const int* __restrict__ finalP,
          float* __restrict__ out)
{
    __shared__ float4 s_u[2][NTHR + 2];

    const int r  = blockIdx.x;
    const int cc = threadIdx.x;

    Ctx c;
    c.idx  = r * NYg + cc;
    c.hasN = (r > 0);
    c.hasS = (r < NXg - 1);
    c.iN   = (r - 1) * NYg + cc;
    c.iS   = (r + 1) * NYg + cc;

    const float Msat = *MsatP;
    c.CEx = (float)(2.0 * 3.5e-12 / ((double)Msat * (5e-8 * 5e-8)));
    c.CD  = (float)(4e-7 * 3.14159265358979323846 * (double)Msat);
    c.hh  = (float)(175950000000.0 * 5e-12);   // GAMMA_LL * DT
    const int final_board = *finalP;

    c.bx = Bext[0 * PLANE + c.idx];
    c.by = Bext[1 * PLANE + c.idx];
    c.bz = Bext[2 * PLANE + c.idx];

    int my_src = -1, my_probe = -1;
    #pragma unroll
    for (int k = 0; k < NSRC; k++)
        if (srcP[2 * k] == r && srcP[2 * k + 1] == cc) my_src = k;
    #pragma unroll
    for (int k = 0; k < NPROBE; k++)
        if (probeP[2 * k] == r && probeP[2 * k + 1] == cc) my_probe = k;

    // Stage counter base: all CTAs end every run at the same value, so bases
    // are uniform across the grid at launch (0 on the first run).
    unsigned scur = g_stage[r];

    // m0 = (0, 1, 0): store + publish (level scur+1)
    float4 m = make_float4(0.0f, 1.0f, 0.0f, 0.0f);
    stage_store(g_m4, c, m, s_u[(scur + 1) & 1]);
    publish_wait(r, scur, c.hasN, c.hasS);

    // ---- relax phase: alpha = 0.5, no source ----
    {
        const float alpha = 0.5f;
        const float inv = 1.0f / (1.0f + alpha * alpha);
        for (int s = 0; s < RELAXN; s++)
            rk4step(m, c, s_u, 0.0f, alpha, inv, r, scur);
    }
    const float4 mr = m;   // m_relaxed (own cell)

    // ---- driven phase: alpha = 0.01 ----
    {
        const float alpha = 0.01f;
        const float inv = 1.0f / (1.0f + alpha * alpha);
        for (int sgn = 0; sgn < NSIG; sgn++) {
            m = mr;
            stage_store(g_m4, c, m, s_u[(scur + 1) & 1]);
            publish_wait(r, scur, c.hasN, c.hasS);
            for (int t = 0; t < TSTEPS; t++) {
                float bzAdd = (my_src >= 0)
                    ? sig[(sgn * TSTEPS + t) * NSRC + my_src] : 0.0f;
                rk4step(m, c, s_u, bzAdd, alpha, inv, r, scur);
                if (my_probe >= 0) {
                    float val = final_board ? (m.z - mr.z) * Msat : m.z;
                    out[(sgn * TSTEPS + t) * NPROBE + my_probe] = val;
                }
            }
        }
    }
}

extern "C" void kernel_launch(void* const* d_in, const int* in_sizes, int n_in,
                              void* d_out, int out_size) {
    const float* sig    = (const float*)d_in[0];  // (2, 256, 3)
    const float* Bext   = (const float*)d_in[1];  // (1, 3, 256, 256)
    const float* MsatP  = (const float*)d_in[2];  // scalar
    const int*   srcP   = (const int*)d_in[3];    // (3, 2)
    const int*   probeP = (const int*)d_in[4];    // (5, 2)
    const int*   finalP = (const int*)d_in[5];    // scalar
    float* out = (float*)d_out;                   // (2, 256, 5)
    (void)in_sizes; (void)n_in; (void)out_size;

    mm_kernel<<<NBLK, NTHR>>>(sig, Bext, MsatP, srcP, probeP, finalP, out);
}

// round 3
// speedup vs baseline: 5.8619x; 5.8619x over previous
#include <cuda_runtime.h>

// Micromagnetic LLG RK4 solver — persistent kernel with HALO (ghost-zone)
// stepping. 128 CTAs x 512 threads: CTA r owns global rows {2r, 2r+1};
// thread (ty = tid>>8, c = tid&255) owns cell (2r+ty, c).
// Each CTA keeps a 10-row window (4-row halo each side) and runs all 4 RK4
// stages locally with a shrinking valid region, so only ONE global barrier
// per RK4 step is needed (613 total instead of 2451).
// Parity scheme: thread handles local rows L = 2k+ty (k=0..4); own row is
// k==2. Own u/m/B_ext stay in registers; W/E neighbors via warp shfl
// (smem fallback at warp-edge lanes); N/S (other parity) via double-buffered
// shared memory. Global exchange is 1 float4 store + 5 float4 loads per
// thread per step.

#define NXg 256
#define NYg 256
#define PLANE (NXg * NYg)
#define TSTEPS 256
#define NSIG 2
#define NSRC 3
#define NPROBE 5
#define RELAXN 100
#define NBLK 128
#define NT 512
#define NROWS 10
#define SROW 258
#define SMEM_BYTES (2 * NROWS * SROW * 16)

__device__ float4 g_m4[PLANE];
__device__ unsigned g_cnt = 0;
__device__ volatile unsigned g_gen = 0;

// Grid barrier (round-1 pattern, proven): elected atomic arrive +
// generation spin. 128 arrivals, all CTAs resident -> no deadlock.
__device__ __forceinline__ void gridbar() {
    __syncthreads();
    if (threadIdx.x == 0) {
        __threadfence();
        unsigned gen = g_gen;
        if (atomicInc(&g_cnt, NBLK - 1u) == NBLK - 1u) {
            g_gen = gen + 1u;
        } else {
            while (g_gen == gen) { }
        }
        __threadfence();
    }
    __syncthreads();
}

__device__ __forceinline__ float3 lap_torque(
    float ux, float uy, float uz,
    float sx, float sy, float sz,          // N+S+W+E sums
    float bx, float by, float bz_, float bzAdd,
    float CEx, float CD, float alpha, float inv)
{
    float lx = sx - 4.0f * ux, ly = sy - 4.0f * uy, lz = sz - 4.0f * uz;
    float Bx = bx + CEx * lx;
    float By = by + CEx * ly;
    float Bz = bz_ + bzAdd + CEx * lz - CD * uz;
    float c1x = uy * Bz - uz * By;
    float c1y = uz * Bx - ux * Bz;
    float c1z = ux * By - uy * Bx;
    float c2x = uy * c1z - uz * c1y;
    float c2y = uz * c1x - ux * c1z;
    float c2z = ux * c1y - uy * c1x;
    const float CS = 1.0e-4f;
    float3 t;
    t.x = -inv * (c1x + alpha * c2x) + CS * (ux * uy);
    t.y = -inv * (c1y + alpha * c2y) + CS * (-(uz * uz + ux * ux));
    t.z = -inv * (c1z + alpha * c2z) + CS * (uy * uz);
    return t;
}

#define U(b, L) (smf4 + ((b) * NROWS + (L)) * SROW)

// One RK4 stage: compute torque over local rows [s, 9-s] (parity-filtered),
// update u registers + publish to smem buffer ob. k==2 is the owned row.
#define STAGE(s, ib, ob, coefE, wK, LAST)                                      \
  {                                                                            \
    _Pragma("unroll")                                                          \
    for (int k = 0; k < 5; k++) {                                              \
      int L = 2 * k + ty;                                                      \
      if (L >= (s) && L <= 9 - (s)) {                                          \
        float uxk = ux[k], uyk = uy[k], uzk = uz[k];                           \
        float4 nN = U(ib, L - 1)[c + 1];                                       \
        float4 nS = U(ib, L + 1)[c + 1];                                       \
        float wxx = __shfl_up_sync(0xffffffffu, uxk, 1);                       \
        float wyy = __shfl_up_sync(0xffffffffu, uyk, 1);                       \
        float wzz = __shfl_up_sync(0xffffffffu, uzk, 1);                       \
        float exx = __shfl_down_sync(0xffffffffu, uxk, 1);                     \
        float eyy = __shfl_down_sync(0xffffffffu, uyk, 1);                     \
        float ezz = __shfl_down_sync(0xffffffffu, uzk, 1);                     \
        if (lane == 0)  { float4 t4 = U(ib, L)[c];                             \
                          wxx = t4.x; wyy = t4.y; wzz = t4.z; }                \
        if (lane == 31) { float4 t4 = U(ib, L)[c + 2];                         \
                          exx = t4.x; eyy = t4.y; ezz = t4.z; }                \
        float3 kv = lap_torque(uxk, uyk, uzk,                                  \
            nN.x + nS.x + wxx + exx,                                           \
            nN.y + nS.y + wyy + eyy,                                           \
            nN.z + nS.z + wzz + ezz,                                           \
            bxr[k], byr[k], bzr[k], bzadd[k], CEx, CD, alpha, inv);            \
        if (k == 2) { ax += (wK) * kv.x; ay += (wK) * kv.y; az += (wK) * kv.z; } \
        if (!(LAST)) {                                                         \
          float nx2 = mxr[k] + (coefE) * kv.x;                                 \
          float ny2 = myr[k] + (coefE) * kv.y;                                 \
          float nz2 = mzr[k] + (coefE) * kv.z;                                 \
          ux[k] = nx2; uy[k] = ny2; uz[k] = nz2;                               \
          float4 ov = make_float4(nx2, ny2, nz2, 0.0f);                        \
          U(ob, L)[c + 1] = ov;                                                \
          if (c == 0)   U(ob, L)[0]   = ov;                                    \
          if (c == 255) U(ob, L)[257] = ov;                                    \
        }                                                                      \
      }                                                                        \
    }                                                                          \
    __syncthreads();                                                           \
  }

#define RK4STEP()                                                              \
  { float ax = 0.0f, ay = 0.0f, az = 0.0f;                                     \
    STAGE(1, 0, 1, h2, 1.0f, false)                                            \
    STAGE(2, 1, 0, h2, 2.0f, false)                                            \
    STAGE(3, 0, 1, hh, 2.0f, false)                                            \
    STAGE(4, 1, 0, 0.0f, 1.0f, true)                                           \
    mxr[2] += h6 * ax; myr[2] += h6 * ay; mzr[2] += h6 * az; }

// Refresh 10-row window from global after the barrier; leaves u regs,
// m regs and smem buffer 0 ready for the next step's stage 1.
#define RELOAD()                                                               \
  { _Pragma("unroll")                                                          \
    for (int k = 0; k < 5; k++) {                                              \
      int L = 2 * k + ty;                                                      \
      float4 v = __ldcg(&g_m4[growr[k] * NYg + c]);                            \
      mxr[k] = v.x; myr[k] = v.y; mzr[k] = v.z;                                \
      ux[k] = v.x; uy[k] = v.y; uz[k] = v.z;                                   \
      U(0, L)[c + 1] = v;                                                      \
      if (c == 0)   U(0, L)[0]   = v;                                          \
      if (c == 255) U(0, L)[257] = v;                                          \
    }                                                                          \
    __syncthreads(); }

__global__ void __launch_bounds__(NT, 1)
mm_kernel(const float* __restrict__ sig, const float* __restrict__ Bext,
          const float* __restrict__ MsatP, const int* __restrict__ srcP,
          const int* __restrict__ probeP, const int* __restrict__ finalP,
          float* __restrict__ out)
{
    extern __shared__ float4 smf4[];

    const int tid  = threadIdx.x;
    const int c    = tid & 255;
    const int ty   = tid >> 8;
    const int lane = tid & 31;
    const int r    = blockIdx.x;
    const int gown = 2 * r + ty;            // owned global row

    const float Msat = *MsatP;
    const float CEx = (float)(2.0 * 3.5e-12 / ((double)Msat * (5e-8 * 5e-8)));
    const float CD  = (float)(4e-7 * 3.14159265358979323846 * (double)Msat);
    const float hh  = (float)(175950000000.0 * 5e-12);   // GAMMA_LL * DT
    const float h2  = 0.5f * hh;
    const float h6  = hh * (1.0f / 6.0f);
    const int final_board = *finalP;

    // Local rows L = 2k+ty map to global grow[k] = clamp(2r-4+L).
    int growr[5];
    #pragma unroll
    for (int k = 0; k < 5; k++) {
        int g = 2 * r - 4 + 2 * k + ty;
        growr[k] = g < 0 ? 0 : (g > NXg - 1 ? NXg - 1 : g);
    }

    // B_ext at each handled row (constant for whole kernel) -> registers.
    float bxr[5], byr[5], bzr[5];
    #pragma unroll
    for (int k = 0; k < 5; k++) {
        int gi = growr[k] * NYg + c;
        bxr[k] = __ldg(Bext + 0 * PLANE + gi);
        byr[k] = __ldg(Bext + 1 * PLANE + gi);
        bzr[k] = __ldg(Bext + 2 * PLANE + gi);
    }

    // Source-id per handled row (which of the 3 sources sits at (grow,c)).
    int sid[5];
    {
        int s0r = srcP[0], s0c = srcP[1];
        int s1r = srcP[2], s1c = srcP[3];
        int s2r = srcP[4], s2c = srcP[5];
        #pragma unroll
        for (int k = 0; k < 5; k++) {
            int g = growr[k];
            sid[k] = (g == s0r && c == s0c) ? 0 :
                     (g == s1r && c == s1c) ? 1 :
                     (g == s2r && c == s2c) ? 2 : -1;
        }
    }
    // Probe-id at owned cell.
    int pid = -1;
    #pragma unroll
    for (int k = 0; k < NPROBE; k++)
        if (probeP[2 * k] == gown && probeP[2 * k + 1] == c) pid = k;

    float ux[5], uy[5], uz[5];
    float mxr[5], myr[5], mzr[5];
    float bzadd[5];
    #pragma unroll
    for (int k = 0; k < 5; k++) bzadd[k] = 0.0f;

    // ---- init: m0 = (0,1,0) everywhere (no global roundtrip needed) ----
    #pragma unroll
    for (int k = 0; k < 5; k++) {
        int L = 2 * k + ty;
        mxr[k] = 0.0f; myr[k] = 1.0f; mzr[k] = 0.0f;
        ux[k] = 0.0f; uy[k] = 1.0f; uz[k] = 0.0f;
        float4 v = make_float4(0.0f, 1.0f, 0.0f, 0.0f);
        U(0, L)[c + 1] = v;
        if (c == 0)   U(0, L)[0]   = v;
        if (c == 255) U(0, L)[257] = v;
    }
    __syncthreads();

    // ---- relax phase: alpha = 0.5 ----
    {
        const float alpha = 0.5f;
        const float inv = 1.0f / (1.0f + alpha * alpha);
        for (int s = 0; s < RELAXN; s++) {
            RK4STEP();
            __stcg(&g_m4[gown * NYg + c],
                   make_float4(mxr[2], myr[2], mzr[2], 0.0f));
            gridbar();
            RELOAD();
        }
    }
    const float mrx = mxr[2], mry = myr[2], mrz = mzr[2];  // m_relaxed (own)

    // ---- driven phase: alpha = 0.01 ----
    {
        const float alpha = 0.01f;
        const float inv = 1.0f / (1.0f + alpha * alpha);
        for (int sgn = 0; sgn < NSIG; sgn++) {
            if (sgn > 0) {   // reset to m_relaxed (halo picks neighbors' mr)
                __stcg(&g_m4[gown * NYg + c], make_float4(mrx, mry, mrz, 0.0f));
                gridbar();
                RELOAD();
            }
            for (int t = 0; t < TSTEPS; t++) {
                const float* sp = sig + (sgn * TSTEPS + t) * NSRC;
                float sv0 = __ldg(sp + 0), sv1 = __ldg(sp + 1), sv2 = __ldg(sp + 2);
                #pragma unroll
                for (int k = 0; k < 5; k++)
                    bzadd[k] = (sid[k] == 0) ? sv0 :
                               (sid[k] == 1) ? sv1 :
                               (sid[k] == 2) ? sv2 : 0.0f;
                RK4STEP();
                __stcg(&g_m4[gown * NYg + c],
                       make_float4(mxr[2], myr[2], mzr[2], 0.0f));
                if (pid >= 0) {
                    float val = final_board ? (mzr[2] - mrz) * Msat : mzr[2];
                    out[(sgn * TSTEPS + t) * NPROBE + pid] = val;
                }
                gridbar();
                RELOAD();
            }
        }
    }
}

extern "C" void kernel_launch(void* const* d_in, const int* in_sizes, int n_in,
                              void* d_out, int out_size) {
    const float* sig    = (const float*)d_in[0];  // (2, 256, 3)
    const float* Bext   = (const float*)d_in[1];  // (1, 3, 256, 256)
    const float* MsatP  = (const float*)d_in[2];  // scalar
    const int*   srcP   = (const int*)d_in[3];    // (3, 2)
    const int*   probeP = (const int*)d_in[4];    // (5, 2)
    const int*   finalP = (const int*)d_in[5];    // scalar
    float* out = (float*)d_out;                   // (2, 256, 5)
    (void)in_sizes; (void)n_in; (void)out_size;

    static int smem_set = 0;
    if (!smem_set) {
        cudaFuncSetAttribute(mm_kernel,
                             cudaFuncAttributeMaxDynamicSharedMemorySize,
                             SMEM_BYTES);
        smem_set = 1;
    }
    mm_kernel<<<NBLK, NT, SMEM_BYTES>>>(sig, Bext, MsatP, srcP, probeP,
                                        finalP, out);
}

// round 5
// speedup vs baseline: 6.5813x; 1.1227x over previous
#include <cuda_runtime.h>

// Micromagnetic LLG RK4 solver — persistent kernel with HALO (ghost-zone)
// stepping and a TWO-LEVEL tree grid barrier built ONLY from primitives
// proven in rounds 1/3 (atomicInc-with-wrap + volatile generation spin +
// threadfence).
// 128 CTAs x 512 threads: CTA r owns global rows {2r, 2r+1}; thread
// (ty = tid>>8, c = tid&255) owns cell (2r+ty, c). Each CTA keeps a 10-row
// window (4-row halo each side) and runs all 4 RK4 stages locally with a
// shrinking valid region -> ONE global barrier per RK4 step (613 total).
// W/E neighbors now come straight from the smem halo columns (LDS.128)
// instead of warp shuffles — shorter latency chains, fewer instructions.

#define NXg 256
#define NYg 256
#define PLANE (NXg * NYg)
#define TSTEPS 256
#define NSIG 2
#define NSRC 3
#define NPROBE 5
#define RELAXN 100
#define NBLK 128
#define NT 512
#define NROWS 10
#define SROW 258
#define SMEM_BYTES (2 * NROWS * SROW * 16)

__device__ float4 g_m4[PLANE];
__device__ unsigned g_cnt0[8 * 64];      // 8 group counters, 256B apart
__device__ unsigned g_cnt1 = 0;          // top-level counter (8 groups)
__device__ volatile unsigned g_gen = 0;  // generation (release flag)

// Two-level tree barrier. Arrive: 16-way atomicInc on the group counter
// (8 groups proceed concurrently), 16th arrival does the 8-way top-level
// atomicInc, 8th group releases by bumping g_gen. Counters self-reset via
// atomicInc wrap. Spin + fences identical to the proven round-1 barrier.
__device__ __forceinline__ void gridbar(int r) {
    __syncthreads();
    if (threadIdx.x == 0) {
        __threadfence();
        unsigned gen = g_gen;
        unsigned grp = ((unsigned)r >> 4) << 6;
        if (atomicInc(&g_cnt0[grp], 15u) == 15u) {
            if (atomicInc(&g_cnt1, 7u) == 7u) {
                g_gen = gen + 1u;
            } else {
                while (g_gen == gen) { }
            }
        } else {
            while (g_gen == gen) { }
        }
        __threadfence();
    }
    __syncthreads();
}

__device__ __forceinline__ float3 lap_torque(
    float ux, float uy, float uz,
    float sx, float sy, float sz,          // N+S+W+E sums
    float bx, float by, float bz_, float bzAdd,
    float CEx, float CD, float alpha, float inv)
{
    float lx = sx - 4.0f * ux, ly = sy - 4.0f * uy, lz = sz - 4.0f * uz;
    float Bx = bx + CEx * lx;
    float By = by + CEx * ly;
    float Bz = bz_ + bzAdd + CEx * lz - CD * uz;
    float c1x = uy * Bz - uz * By;
    float c1y = uz * Bx - ux * Bz;
    float c1z = ux * By - uy * Bx;
    float c2x = uy * c1z - uz * c1y;
    float c2y = uz * c1x - ux * c1z;
    float c2z = ux * c1y - uy * c1x;
    const float CS = 1.0e-4f;
    float3 t;
    t.x = -inv * (c1x + alpha * c2x) + CS * (ux * uy);
    t.y = -inv * (c1y + alpha * c2y) + CS * (-(uz * uz + ux * ux));
    t.z = -inv * (c1z + alpha * c2z) + CS * (uy * uz);
    return t;
}

#define U(b, L) (smf4 + ((b) * NROWS + (L)) * SROW)

// One RK4 stage: compute torque over local rows [s, 9-s] (parity-filtered),
// update u registers + publish to smem buffer ob. k==2 is the owned row.
// All 4 neighbors come from smem (halo columns 0/257 kept valid by the
// c==0 / c==255 edge stores).
#define STAGE(s, ib, ob, coefE, wK, LAST)                                      \
  {                                                                            \
    _Pragma("unroll")                                                          \
    for (int k = 0; k < 5; k++) {                                              \
      int L = 2 * k + ty;                                                      \
      if (L >= (s) && L <= 9 - (s)) {                                          \
        float4 nN = U(ib, L - 1)[c + 1];                                       \
        float4 nS = U(ib, L + 1)[c + 1];                                       \
        float4 nW = U(ib, L)[c];                                               \
        float4 nE = U(ib, L)[c + 2];                                           \
        float3 kv = lap_torque(ux[k], uy[k], uz[k],                            \
            nN.x + nS.x + nW.x + nE.x,                                         \
            nN.y + nS.y + nW.y + nE.y,                                         \
            nN.z + nS.z + nW.z + nE.z,                                         \
            bxr[k], byr[k], bzr[k], bzadd[k], CEx, CD, alpha, inv);            \
        if (k == 2) { ax += (wK) * kv.x; ay += (wK) * kv.y; az += (wK) * kv.z; } \
        if (!(LAST)) {                                                         \
          float nx2 = mxr[k] + (coefE) * kv.x;                                 \
          float ny2 = myr[k] + (coefE) * kv.y;                                 \
          float nz2 = mzr[k] + (coefE) * kv.z;                                 \
          ux[k] = nx2; uy[k] = ny2; uz[k] = nz2;                               \
          float4 ov = make_float4(nx2, ny2, nz2, 0.0f);                        \
          U(ob, L)[c + 1] = ov;                                                \
          if (c == 0)   U(ob, L)[0]   = ov;                                    \
          if (c == 255) U(ob, L)[257] = ov;                                    \
        }                                                                      \
      }                                                                        \
    }                                                                          \
    __syncthreads();                                                           \
  }

#define RK4STEP()                                                              \
  { float ax = 0.0f, ay = 0.0f, az = 0.0f;                                     \
    STAGE(1, 0, 1, h2, 1.0f, false)                                            \
    STAGE(2, 1, 0, h2, 2.0f, false)                                            \
    STAGE(3, 0, 1, hh, 2.0f, false)                                            \
    STAGE(4, 1, 0, 0.0f, 1.0f, true)                                           \
    mxr[2] += h6 * ax; myr[2] += h6 * ay; mzr[2] += h6 * az; }

// Refresh 10-row window after the barrier. Halo rows (k != 2) from global;
// own row (k == 2) straight from registers (value just stored to global).
#define RELOAD()                                                               \
  { _Pragma("unroll")                                                          \
    for (int k = 0; k < 5; k++) {                                              \
      int L = 2 * k + ty;                                                      \
      float4 v;                                                                \
      if (k == 2) v = make_float4(mxr[2], myr[2], mzr[2], 0.0f);               \
      else        v = __ldcg(&g_m4[growr[k] * NYg + c]);                       \
      mxr[k] = v.x; myr[k] = v.y; mzr[k] = v.z;                                \
      ux[k] = v.x; uy[k] = v.y; uz[k] = v.z;                                   \
      U(0, L)[c + 1] = v;                                                      \
      if (c == 0)   U(0, L)[0]   = v;                                          \
      if (c == 255) U(0, L)[257] = v;                                          \
    }                                                                          \
    __syncthreads(); }

__global__ void __launch_bounds__(NT, 1)
mm_kernel(const float* __restrict__ sig, const float* __restrict__ Bext,
          const float* __restrict__ MsatP, const int* __restrict__ srcP,
          const int* __restrict__ probeP, const int* __restrict__ finalP,
          float* __restrict__ out)
{
    extern __shared__ float4 smf4[];

    const int tid  = threadIdx.x;
    const int c    = tid & 255;
    const int ty   = tid >> 8;
    const int r    = blockIdx.x;
    const int gown = 2 * r + ty;            // owned global row

    const float Msat = *MsatP;
    const float CEx = (float)(2.0 * 3.5e-12 / ((double)Msat * (5e-8 * 5e-8)));
    const float CD  = (float)(4e-7 * 3.14159265358979323846 * (double)Msat);
    const float hh  = (float)(175950000000.0 * 5e-12);   // GAMMA_LL * DT
    const float h2  = 0.5f * hh;
    const float h6  = hh * (1.0f / 6.0f);
    const int final_board = *finalP;

    // Local rows L = 2k+ty map to global grow[k] = clamp(2r-4+L).
    int growr[5];
    #pragma unroll
    for (int k = 0; k < 5; k++) {
        int g = 2 * r - 4 + 2 * k + ty;
        growr[k] = g < 0 ? 0 : (g > NXg - 1 ? NXg - 1 : g);
    }

    // B_ext at each handled row (constant for whole kernel) -> registers.
    float bxr[5], byr[5], bzr[5];
    #pragma unroll
    for (int k = 0; k < 5; k++) {
        int gi = growr[k] * NYg + c;
        bxr[k] = __ldg(Bext + 0 * PLANE + gi);
        byr[k] = __ldg(Bext + 1 * PLANE + gi);
        bzr[k] = __ldg(Bext + 2 * PLANE + gi);
    }

    // Source-id per handled row.
    int sid[5];
    {
        int s0r = srcP[0], s0c = srcP[1];
        int s1r = srcP[2], s1c = srcP[3];
        int s2r = srcP[4], s2c = srcP[5];
        #pragma unroll
        for (int k = 0; k < 5; k++) {
            int g = growr[k];
            sid[k] = (g == s0r && c == s0c) ? 0 :
                     (g == s1r && c == s1c) ? 1 :
                     (g == s2r && c == s2c) ? 2 : -1;
        }
    }
    // Probe-id at owned cell.
    int pid = -1;
    #pragma unroll
    for (int k = 0; k < NPROBE; k++)
        if (probeP[2 * k] == gown && probeP[2 * k + 1] == c) pid = k;

    float ux[5], uy[5], uz[5];
    float mxr[5], myr[5], mzr[5];
    float bzadd[5];
    #pragma unroll
    for (int k = 0; k < 5; k++) bzadd[k] = 0.0f;

    // ---- init: m0 = (0,1,0) everywhere ----
    #pragma unroll
    for (int k = 0; k < 5; k++) {
        int L = 2 * k + ty;
        mxr[k] = 0.0f; myr[k] = 1.0f; mzr[k] = 0.0f;
        ux[k] = 0.0f; uy[k] = 1.0f; uz[k] = 0.0f;
        float4 v = make_float4(0.0f, 1.0f, 0.0f, 0.0f);
        U(0, L)[c + 1] = v;
        if (c == 0)   U(0, L)[0]   = v;
        if (c == 255) U(0, L)[257] = v;
    }
    __syncthreads();

    // ---- relax phase: alpha = 0.5 ----
    {
        const float alpha = 0.5f;
        const float inv = 1.0f / (1.0f + alpha * alpha);
        for (int s = 0; s < RELAXN; s++) {
            RK4STEP();
            __stcg(&g_m4[gown * NYg + c],
                   make_float4(mxr[2], myr[2], mzr[2], 0.0f));
            gridbar(r);
            RELOAD();
        }
    }
    const float mrx = mxr[2], mry = myr[2], mrz = mzr[2];  // m_relaxed (own)

    // ---- driven phase: alpha = 0.01 ----
    {
        const float alpha = 0.01f;
        const float inv = 1.0f / (1.0f + alpha * alpha);
        for (int sgn = 0; sgn < NSIG; sgn++) {
            if (sgn > 0) {   // reset to m_relaxed
                mxr[2] = mrx; myr[2] = mry; mzr[2] = mrz;
                __stcg(&g_m4[gown * NYg + c], make_float4(mrx, mry, mrz, 0.0f));
                gridbar(r);
                RELOAD();
            }
            for (int t = 0; t < TSTEPS; t++) {
                const float* sp = sig + (sgn * TSTEPS + t) * NSRC;
                float sv0 = __ldg(sp + 0), sv1 = __ldg(sp + 1), sv2 = __ldg(sp + 2);
                #pragma unroll
                for (int k = 0; k < 5; k++)
                    bzadd[k] = (sid[k] == 0) ? sv0 :
                               (sid[k] == 1) ? sv1 :
                               (sid[k] == 2) ? sv2 : 0.0f;
                RK4STEP();
                __stcg(&g_m4[gown * NYg + c],
                       make_float4(mxr[2], myr[2], mzr[2], 0.0f));
                if (pid >= 0) {
                    float val = final_board ? (mzr[2] - mrz) * Msat : mzr[2];
                    out[(sgn * TSTEPS + t) * NPROBE + pid] = val;
                }
                gridbar(r);
                RELOAD();
            }
        }
    }
}

extern "C" void kernel_launch(void* const* d_in, const int* in_sizes, int n_in,
                              void* d_out, int out_size) {
    const float* sig    = (const float*)d_in[0];  // (2, 256, 3)
    const float* Bext   = (const float*)d_in[1];  // (1, 3, 256, 256)
    const float* MsatP  = (const float*)d_in[2];  // scalar
    const int*   srcP   = (const int*)d_in[3];    // (3, 2)
    const int*   probeP = (const int*)d_in[4];    // (5, 2)
    const int*   finalP = (const int*)d_in[5];    // scalar
    float* out = (float*)d_out;                   // (2, 256, 5)
    (void)in_sizes; (void)n_in; (void)out_size;

    cudaFuncSetAttribute(mm_kernel,
                         cudaFuncAttributeMaxDynamicSharedMemorySize,
                         SMEM_BYTES);
    mm_kernel<<<NBLK, NT, SMEM_BYTES>>>(sig, Bext, MsatP, srcP, probeP,
                                        finalP, out);
}

// round 6
// speedup vs baseline: 6.7056x; 1.0189x over previous
#include <cuda_runtime.h>

// Micromagnetic LLG RK4 solver — persistent kernel, halo stepping, tree
// barrier (proven R5), and VERTICAL-STRIP register mapping:
// 128 CTAs x 512 threads; CTA r owns global rows {2r, 2r+1}. The CTA's
// 10-row window (4-row halo each side) is split into two 5-row strips:
// thread (ty = tid>>8, c = tid&255) holds window rows 5ty..5ty+4 in
// REGISTERS. Vertical (N/S) neighbors are register reads for interior rows;
// only the strip boundary (window rows 4<->5) crosses threads via smem
// (one LDS per stage). W/E neighbors come from the smem halo-column rows.
// Per-stage validity is warp-uniform: ty0 computes k>=s, ty1 k<=4-s.

#define NXg 256
#define NYg 256
#define PLANE (NXg * NYg)
#define TSTEPS 256
#define NSIG 2
#define NSRC 3
#define NPROBE 5
#define RELAXN 100
#define NBLK 128
#define NT 512
#define NROWS 10
#define SROW 258
#define SMEM_BYTES (2 * NROWS * SROW * 16)

__device__ float4 g_m4[PLANE];
__device__ unsigned g_cnt0[8 * 64];      // 8 group counters, 256B apart
__device__ unsigned g_cnt1 = 0;          // top-level counter (8 groups)
__device__ volatile unsigned g_gen = 0;  // generation (release flag)

// Two-level tree barrier (proven round 5): 16-way group atomicInc (8 groups
// concurrent), 16th arrival does the 8-way top-level inc, last releases.
__device__ __forceinline__ void gridbar(int r) {
    __syncthreads();
    if (threadIdx.x == 0) {
        __threadfence();
        unsigned gen = g_gen;
        unsigned grp = ((unsigned)r >> 4) << 6;
        if (atomicInc(&g_cnt0[grp], 15u) == 15u) {
            if (atomicInc(&g_cnt1, 7u) == 7u) {
                g_gen = gen + 1u;
            } else {
                while (g_gen == gen) { }
            }
        } else {
            while (g_gen == gen) { }
        }
        __threadfence();
    }
    __syncthreads();
}

__device__ __forceinline__ float3 lap_torque(
    float ux, float uy, float uz,
    float sx, float sy, float sz,          // N+S+W+E sums
    float bx, float by, float bz_, float bzAdd,
    float CEx, float CD, float alpha, float inv)
{
    float lx = sx - 4.0f * ux, ly = sy - 4.0f * uy, lz = sz - 4.0f * uz;
    float Bx = bx + CEx * lx;
    float By = by + CEx * ly;
    float Bz = bz_ + bzAdd + CEx * lz - CD * uz;
    float c1x = uy * Bz - uz * By;
    float c1y = uz * Bx - ux * Bz;
    float c1z = ux * By - uy * Bx;
    float c2x = uy * c1z - uz * c1y;
    float c2y = uz * c1x - ux * c1z;
    float c2z = ux * c1y - uy * c1x;
    const float CS = 1.0e-4f;
    float3 t;
    t.x = -inv * (c1x + alpha * c2x) + CS * (ux * uy);
    t.y = -inv * (c1y + alpha * c2y) + CS * (-(uz * uz + ux * ux));
    t.z = -inv * (c1z + alpha * c2z) + CS * (uy * uz);
    return t;
}

#define U(b, L) (smf4 + ((b) * NROWS + (L)) * SROW)

// One RK4 stage under the strip mapping. Valid rows: ty0 k>=s, ty1 k<=4-s.
// N neighbor of k: reg k-1, except ty1 k==0 -> boundary row 4 (smem).
// S neighbor of k: reg k+1, except ty0 k==4 -> boundary row 5 (smem).
// (The never-valid combinations ty0 k==0 / ty1 k==4 hide behind `valid`.)
#define STAGE(s, ib, ob, coefE, wK, LAST)                                      \
  {                                                                            \
    float4 bnd = U(ib, bndL)[c + 1];                                           \
    _Pragma("unroll")                                                          \
    for (int k = 0; k < 5; k++) {                                              \
      bool valid = ty ? (k <= 4 - (s)) : (k >= (s));                           \
      if (valid) {                                                             \
        int L = lbase + k;                                                     \
        float nNx = (k > 0) ? ux[k - 1] : bnd.x;                               \
        float nNy = (k > 0) ? uy[k - 1] : bnd.y;                               \
        float nNz = (k > 0) ? uz[k - 1] : bnd.z;                               \
        float nSx = (k < 4) ? ux[k + 1] : bnd.x;                               \
        float nSy = (k < 4) ? uy[k + 1] : bnd.y;                               \
        float nSz = (k < 4) ? uz[k + 1] : bnd.z;                               \
        float4 nW = U(ib, L)[c];                                               \
        float4 nE = U(ib, L)[c + 2];                                           \
        float3 kv = lap_torque(ux[k], uy[k], uz[k],                            \
            nNx + nSx + nW.x + nE.x,                                           \
            nNy + nSy + nW.y + nE.y,                                           \
            nNz + nSz + nW.z + nE.z,                                           \
            bxr[k], byr[k], bzr[k], bzadd[k], CEx, CD, alpha, inv);            \
        if (k == kown) { ax += (wK) * kv.x; ay += (wK) * kv.y;                 \
                         az += (wK) * kv.z; }                                  \
        if (!(LAST)) {                                                         \
          float nx2 = mxr[k] + (coefE) * kv.x;                                 \
          float ny2 = myr[k] + (coefE) * kv.y;                                 \
          float nz2 = mzr[k] + (coefE) * kv.z;                                 \
          vx[k] = nx2; vy[k] = ny2; vz[k] = nz2;                               \
          float4 ov = make_float4(nx2, ny2, nz2, 0.0f);                        \
          U(ob, L)[c + 1] = ov;                                                \
          if (c == 0)   U(ob, L)[0]   = ov;                                    \
          if (c == 255) U(ob, L)[257] = ov;                                    \
        }                                                                      \
      }                                                                        \
    }                                                                          \
    _Pragma("unroll")                                                          \
    for (int k = 0; k < 5; k++) { ux[k] = vx[k]; uy[k] = vy[k];                \
                                  uz[k] = vz[k]; }                             \
    __syncthreads();                                                           \
  }

#define RK4STEP()                                                              \
  { float ax = 0.0f, ay = 0.0f, az = 0.0f;                                     \
    STAGE(1, 0, 1, h2, 1.0f, false)                                            \
    STAGE(2, 1, 0, h2, 2.0f, false)                                            \
    STAGE(3, 0, 1, hh, 2.0f, false)                                            \
    STAGE(4, 1, 0, 0.0f, 1.0f, true)                                           \
    mxr[kown] += h6 * ax; myr[kown] += h6 * ay; mzr[kown] += h6 * az; }

// Refresh the strip after the barrier: halo rows from global, own row from
// registers. Repopulate smem buffer 0 for the next step's stage 1.
#define RELOAD()                                                               \
  { _Pragma("unroll")                                                          \
    for (int k = 0; k < 5; k++) {                                              \
      int L = lbase + k;                                                       \
      float4 v;                                                                \
      if (k == kown) v = make_float4(mxr[k], myr[k], mzr[k], 0.0f);            \
      else           v = __ldcg(&g_m4[growr[k] * NYg + c]);                    \
      mxr[k] = v.x; myr[k] = v.y; mzr[k] = v.z;                                \
      ux[k] = v.x; uy[k] = v.y; uz[k] = v.z;                                   \
      vx[k] = v.x; vy[k] = v.y; vz[k] = v.z;                                   \
      U(0, L)[c + 1] = v;                                                      \
      if (c == 0)   U(0, L)[0]   = v;                                          \
      if (c == 255) U(0, L)[257] = v;                                          \
    }                                                                          \
    __syncthreads(); }

__global__ void __launch_bounds__(NT, 1)
mm_kernel(const float* __restrict__ sig, const float* __restrict__ Bext,
          const float* __restrict__ MsatP, const int* __restrict__ srcP,
          const int* __restrict__ probeP, const int* __restrict__ finalP,
          float* __restrict__ out)
{
    extern __shared__ float4 smf4[];

    const int tid   = threadIdx.x;
    const int c     = tid & 255;
    const int ty    = tid >> 8;
    const int r     = blockIdx.x;
    const int lbase = 5 * ty;              // strip start (window row)
    const int kown  = ty ? 0 : 4;          // owned row's k (window row 4/5)
    const int bndL  = ty ? 4 : 5;          // cross-strip boundary row
    const int gown  = 2 * r + ty;          // owned global row

    const float Msat = *MsatP;
    const float CEx = (float)(2.0 * 3.5e-12 / ((double)Msat * (5e-8 * 5e-8)));
    const float CD  = (float)(4e-7 * 3.14159265358979323846 * (double)Msat);
    const float hh  = (float)(175950000000.0 * 5e-12);   // GAMMA_LL * DT
    const float h2  = 0.5f * hh;
    const float h6  = hh * (1.0f / 6.0f);
    const int final_board = *finalP;

    // Strip rows map to global grow[k] = clamp(2r - 4 + lbase + k).
    int growr[5];
    #pragma unroll
    for (int k = 0; k < 5; k++) {
        int g = 2 * r - 4 + lbase + k;
        growr[k] = g < 0 ? 0 : (g > NXg - 1 ? NXg - 1 : g);
    }

    // B_ext per strip row -> registers.
    float bxr[5], byr[5], bzr[5];
    #pragma unroll
    for (int k = 0; k < 5; k++) {
        int gi = growr[k] * NYg + c;
        bxr[k] = __ldg(Bext + 0 * PLANE + gi);
        byr[k] = __ldg(Bext + 1 * PLANE + gi);
        bzr[k] = __ldg(Bext + 2 * PLANE + gi);
    }

    // Source-id per strip row.
    int sid[5];
    {
        int s0r = srcP[0], s0c = srcP[1];
        int s1r = srcP[2], s1c = srcP[3];
        int s2r = srcP[4], s2c = srcP[5];
        #pragma unroll
        for (int k = 0; k < 5; k++) {
            int g = growr[k];
            sid[k] = (g == s0r && c == s0c) ? 0 :
                     (g == s1r && c == s1c) ? 1 :
                     (g == s2r && c == s2c) ? 2 : -1;
        }
    }
    // Probe-id at owned cell.
    int pid = -1;
    #pragma unroll
    for (int k = 0; k < NPROBE; k++)
        if (probeP[2 * k] == gown && probeP[2 * k + 1] == c) pid = k;

    float ux[5], uy[5], uz[5];          // stage-input values
    float vx[5], vy[5], vz[5];          // stage-output staging
    float mxr[5], myr[5], mzr[5];       // base m for this step
    float bzadd[5];
    #pragma unroll
    for (int k = 0; k < 5; k++) bzadd[k] = 0.0f;

    // ---- init: m0 = (0,1,0) everywhere ----
    #pragma unroll
    for (int k = 0; k < 5; k++) {
        int L = lbase + k;
        mxr[k] = 0.0f; myr[k] = 1.0f; mzr[k] = 0.0f;
        ux[k] = 0.0f; uy[k] = 1.0f; uz[k] = 0.0f;
        vx[k] = 0.0f; vy[k] = 1.0f; vz[k] = 0.0f;
        float4 v = make_float4(0.0f, 1.0f, 0.0f, 0.0f);
        U(0, L)[c + 1] = v;
        if (c == 0)   U(0, L)[0]   = v;
        if (c == 255) U(0, L)[257] = v;
    }
    __syncthreads();

    // ---- relax phase: alpha = 0.5 ----
    {
        const float alpha = 0.5f;
        const float inv = 1.0f / (1.0f + alpha * alpha);
        for (int s = 0; s < RELAXN; s++) {
            RK4STEP();
            __stcg(&g_m4[gown * NYg + c],
                   make_float4(mxr[kown], myr[kown], mzr[kown], 0.0f));
            gridbar(r);
            RELOAD();
        }
    }
    const float mrx = mxr[kown], mry = myr[kown], mrz = mzr[kown];

    // ---- driven phase: alpha = 0.01 ----
    {
        const float alpha = 0.01f;
        const float inv = 1.0f / (1.0f + alpha * alpha);
        for (int sgn = 0; sgn < NSIG; sgn++) {
            if (sgn > 0) {   // reset to m_relaxed
                mxr[kown] = mrx; myr[kown] = mry; mzr[kown] = mrz;
                __stcg(&g_m4[gown * NYg + c], make_float4(mrx, mry, mrz, 0.0f));
                gridbar(r);
                RELOAD();
            }
            for (int t = 0; t < TSTEPS; t++) {
                const float* sp = sig + (sgn * TSTEPS + t) * NSRC;
                float sv0 = __ldg(sp + 0), sv1 = __ldg(sp + 1), sv2 = __ldg(sp + 2);
                #pragma unroll
                for (int k = 0; k < 5; k++)
                    bzadd[k] = (sid[k] == 0) ? sv0 :
                               (sid[k] == 1) ? sv1 :
                               (sid[k] == 2) ? sv2 : 0.0f;
                RK4STEP();
                __stcg(&g_m4[gown * NYg + c],
                       make_float4(mxr[kown], myr[kown], mzr[kown], 0.0f));
                if (pid >= 0) {
                    float val = final_board ? (mzr[kown] - mrz) * Msat
                                            : mzr[kown];
                    out[(sgn * TSTEPS + t) * NPROBE + pid] = val;
                }
                gridbar(r);
                RELOAD();
            }
        }
    }
}

extern "C" void kernel_launch(void* const* d_in, const int* in_sizes, int n_in,
                              void* d_out, int out_size) {
    const float* sig    = (const float*)d_in[0];  // (2, 256, 3)
    const float* Bext   = (const float*)d_in[1];  // (1, 3, 256, 256)
    const float* MsatP  = (const float*)d_in[2];  // scalar
    const int*   srcP   = (const int*)d_in[3];    // (3, 2)
    const int*   probeP = (const int*)d_in[4];    // (5, 2)
    const int*   finalP = (const int*)d_in[5];    // scalar
    float* out = (float*)d_out;                   // (2, 256, 5)
    (void)in_sizes; (void)n_in; (void)out_size;

    cudaFuncSetAttribute(mm_kernel,
                         cudaFuncAttributeMaxDynamicSharedMemorySize,
                         SMEM_BYTES);
    mm_kernel<<<NBLK, NT, SMEM_BYTES>>>(sig, Bext, MsatP, srcP, probeP,
                                        finalP, out);
}